// round 16
// baseline (speedup 1.0000x reference)
#include <cuda_runtime.h>
#include <math.h>

#define NLVL 4
#define HD   1024
#define SEQ  512
#define NBLK 128
#define NTHR 256
#define NWARP 8
#define FLAGF 2.0f            // impossible h value: |h| < 1 always

// ---------------- device scratch (static, no allocation) ----------------
__device__ __align__(16) float B_G   [SEQ * HD];      // gelu intermediate buffer
__device__ __align__(16) float B_ENC0[SEQ * HD];
__device__ __align__(16) float B_ENC1[SEQ * HD];
__device__ __align__(16) float B_ENC2[SEQ * HD];
__device__ __align__(16) float B_ENC3[SEQ * HD];
__device__ __align__(16) float B_P1  [SEQ * HD];
__device__ __align__(16) float B_P2  [SEQ * HD];
__device__ __align__(16) float B_P3  [SEQ * HD];
__device__ __align__(16) float B_H0  [SEQ * HD];
__device__ __align__(16) float B_H1  [SEQ * HD];
__device__ __align__(16) float B_H2  [SEQ * HD];
__device__ __align__(16) float B_PE  [SEQ * HD];      // prec * enc (per level, reused)
__device__ float B_DOT[SEQ];                           // err.qw per t (per level, reused)
__device__ float B_fe [4 * SEQ];                       // per-level per-t fe terms
__device__ float B_prec_unused[SEQ];

// ---------------- helpers ----------------
__device__ __forceinline__ float gelu_f(float x) {
    return 0.5f * x * (1.0f + erff(x * 0.7071067811865475f));
}
__device__ __forceinline__ float sigm(float x) {
    return 1.0f / (1.0f + __expf(-x));
}
// fast MUFU-based activations for the chain critical path (~1e-6 rel err)
__device__ __forceinline__ float sigm_fast(float x) {
    return __fdividef(1.0f, 1.0f + __expf(-x));
}
__device__ __forceinline__ float tanh_fast(float x) {
    return 1.0f - __fdividef(2.0f, __expf(2.0f * x) + 1.0f);
}

// morally-strong (coherent) GPU-scope ops — per-location coherence is only
// guaranteed for .relaxed/.acquire/.release scoped ops (weak .cg reads stale).
__device__ __forceinline__ float ld_relaxed(const float* p) {
    float v;
    asm volatile("ld.relaxed.gpu.global.f32 %0, [%1];" : "=f"(v) : "l"(p) : "memory");
    return v;
}
__device__ __forceinline__ void st_release(float* p, float v) {
    asm volatile("st.release.gpu.global.f32 [%0], %1;" :: "l"(p), "f"(v) : "memory");
}

// block reduce; result valid in thread 0
__device__ __forceinline__ float block_reduce(float v, float* sred) {
#pragma unroll
    for (int o = 16; o; o >>= 1) v += __shfl_xor_sync(0xffffffffu, v, o);
    int w = threadIdx.x >> 5;
    if ((threadIdx.x & 31) == 0) sred[w] = v;
    __syncthreads();
    if (threadIdx.x < 32) {
        v = (threadIdx.x < NWARP) ? sred[threadIdx.x] : 0.0f;
#pragma unroll
        for (int o = 4; o; o >>= 1) v += __shfl_xor_sync(0xffffffffu, v, o);
    }
    __syncthreads();
    return v;
}

// ---------------- flag prefill + fe zero (runs every replay, first) ------
__global__ void flag_fill() {
    size_t i = (size_t)blockIdx.x * blockDim.x + threadIdx.x;
    if (i < (size_t)SEQ * HD) {
        B_H0[i] = FLAGF; B_H1[i] = FLAGF; B_H2[i] = FLAGF;
    }
    if (i < 3 * SEQ) B_fe[SEQ + i] = 0.0f;   // zero levels 1..3 fe accumulators
}

// ---------------- tiled GEMM: 64 timesteps x 64 rows, double-buffered ----
// out[t][r] = act( W[r]·x_t + bias[r] ),  x_t = inA[t] (- inB[t] if inB)
// Optional fused stages:
//  qwl/dotout   (ew1 mode): block column 0 also computes dot(x_t, qwl) per t
//                           (x is the err vector) -> dotout[t], no atomics.
//  dotin/qbl/peout/feout (ew2 mode): epilogue computes prec=sigm(dot+qb),
//                           stores PE = out*prec, atomically accumulates
//                           fe[t] += prec * sum(out^2).
__global__ void __launch_bounds__(256) gemm_k(
    const float* __restrict__ W,    const float* __restrict__ bias,
    const float* __restrict__ inA,  const float* __restrict__ inB,
    float* __restrict__ outp, int out_gelu,
    const float* __restrict__ qwl,  float* __restrict__ dotout,
    const float* __restrict__ dotin, const float* __restrict__ qbl,
    float* __restrict__ peout, float* __restrict__ feout) {
    __shared__ __align__(16) float As[2][16][68];   // [buf][k][t]
    __shared__ __align__(16) float Bs[2][16][68];   // [buf][k][r]
    const int tid = threadIdx.x;
    const int bm = blockIdx.y * 64;              // timestep tile
    const int bn = blockIdx.x * 64;              // row tile
    const int tm = (tid >> 4) << 2;              // 4 t per thread
    const int tn = (tid & 15) << 2;              // 4 rows per thread
    const int lrow = tid >> 2, lk = (tid & 3) << 2;

    const float* Arow = inA + (size_t)(bm + lrow) * HD;
    const float* Brow = inB ? (inB + (size_t)(bm + lrow) * HD) : nullptr;
    const float* Wrow = W + (size_t)(bn + lrow) * HD;
    const bool dodot = (dotout != nullptr) && (blockIdx.x == 0);
    float dq = 0.0f;

    // prologue: load tile 0 into buffer 0
    {
        float4 a = *(const float4*)(Arow + lk);
        if (Brow) {
            float4 b2 = *(const float4*)(Brow + lk);
            a.x -= b2.x; a.y -= b2.y; a.z -= b2.z; a.w -= b2.w;
        }
        if (dodot) {
            float4 q = *(const float4*)(qwl + lk);
            dq = a.x * q.x + a.y * q.y + a.z * q.z + a.w * q.w;
        }
        float4 w4 = *(const float4*)(Wrow + lk);
        As[0][lk + 0][lrow] = a.x; As[0][lk + 1][lrow] = a.y;
        As[0][lk + 2][lrow] = a.z; As[0][lk + 3][lrow] = a.w;
        Bs[0][lk + 0][lrow] = w4.x; Bs[0][lk + 1][lrow] = w4.y;
        Bs[0][lk + 2][lrow] = w4.z; Bs[0][lk + 3][lrow] = w4.w;
    }
    __syncthreads();

    float acc[4][4] = {};
#pragma unroll 2
    for (int i = 0; i < HD / 16; i++) {
        const int buf = i & 1;
        const bool more = (i + 1 < HD / 16);
        // prefetch tile i+1 into registers (overlaps with compute below)
        float4 an = make_float4(0.f, 0.f, 0.f, 0.f);
        float4 wn = make_float4(0.f, 0.f, 0.f, 0.f);
        if (more) {
            const int k0 = (i + 1) * 16;
            an = *(const float4*)(Arow + k0 + lk);
            if (Brow) {
                float4 b2 = *(const float4*)(Brow + k0 + lk);
                an.x -= b2.x; an.y -= b2.y; an.z -= b2.z; an.w -= b2.w;
            }
            if (dodot) {
                float4 q = *(const float4*)(qwl + k0 + lk);
                dq += an.x * q.x + an.y * q.y + an.z * q.z + an.w * q.w;
            }
            wn = *(const float4*)(Wrow + k0 + lk);
        }
        // compute on buffer buf
#pragma unroll
        for (int k = 0; k < 16; k++) {
            float4 a4 = *(const float4*)&As[buf][k][tm];
            float4 b4 = *(const float4*)&Bs[buf][k][tn];
            float arr[4] = {a4.x, a4.y, a4.z, a4.w};
            float brr[4] = {b4.x, b4.y, b4.z, b4.w};
#pragma unroll
            for (int ii = 0; ii < 4; ii++)
#pragma unroll
                for (int jj = 0; jj < 4; jj++)
                    acc[ii][jj] = fmaf(arr[ii], brr[jj], acc[ii][jj]);
        }
        if (more) {
            const int nb = buf ^ 1;
            As[nb][lk + 0][lrow] = an.x; As[nb][lk + 1][lrow] = an.y;
            As[nb][lk + 2][lrow] = an.z; As[nb][lk + 3][lrow] = an.w;
            Bs[nb][lk + 0][lrow] = wn.x; Bs[nb][lk + 1][lrow] = wn.y;
            Bs[nb][lk + 2][lrow] = wn.z; Bs[nb][lk + 3][lrow] = wn.w;
            __syncthreads();
        }
    }

    // fused dot reduction (4 threads per t, consecutive lanes)
    if (dodot) {
        dq += __shfl_xor_sync(0xffffffffu, dq, 1);
        dq += __shfl_xor_sync(0xffffffffu, dq, 2);
        if ((tid & 3) == 0) dotout[bm + lrow] = dq;
    }

    const float4 bb = *(const float4*)&bias[bn + tn];
    const float qb0 = qbl ? __ldg(qbl) : 0.0f;
#pragma unroll
    for (int i = 0; i < 4; i++) {
        float4 v;
        v.x = acc[i][0] + bb.x; v.y = acc[i][1] + bb.y;
        v.z = acc[i][2] + bb.z; v.w = acc[i][3] + bb.w;
        if (out_gelu) {
            v.x = gelu_f(v.x); v.y = gelu_f(v.y);
            v.z = gelu_f(v.z); v.w = gelu_f(v.w);
        }
        const int t = bm + tm + i;
        *(float4*)&outp[(size_t)t * HD + bn + tn] = v;
        if (peout) {
            float prec = sigm_fast(__ldg(&dotin[t]) + qb0);
            float4 pe;
            pe.x = v.x * prec; pe.y = v.y * prec;
            pe.z = v.z * prec; pe.w = v.w * prec;
            *(float4*)&peout[(size_t)t * HD + bn + tn] = pe;
            float s2 = v.x * v.x + v.y * v.y + v.z * v.z + v.w * v.w;
            atomicAdd(&feout[t], prec * s2);
        }
    }
}

// ---------------- level-0 aux: prec0/PE0/fe0 (unchanged, proven) ---------
__global__ void __launch_bounds__(NTHR) lvl0_aux(const float* __restrict__ obs,
                                                 const float* __restrict__ qw,
                                                 const float* __restrict__ qb) {
    __shared__ float sred[NWARP];
    __shared__ float sprec;
    const int t = blockIdx.x, tid = threadIdx.x;
    float d = 0.0f;
    for (int i = tid; i < HD; i += NTHR)
        d = fmaf(obs[(size_t)t * HD + i], qw[i], d);
    d = block_reduce(d, sred);
    if (tid == 0) sprec = sigm(d + qb[0]);
    __syncthreads();
    float prec = sprec, s = 0.0f;
    for (int i = tid; i < HD; i += NTHR) {
        float e = B_ENC0[(size_t)t * HD + i];
        B_PE[(size_t)t * HD + i] = e * prec;
        s = fmaf(e, e, s);
    }
    s = block_reduce(s, sred);
    if (tid == 0) B_fe[t] = s * prec;
}

// ---------------- sequential LSTM chain (round-12 proven; FROZEN) ---------
// gates(t) = wih @ (h(t-1) + pe(t)) + (bih+bhh)  [C-GEMM folded in].
// warp gw owns W rows {gw, gw+2HD, gw+3HD} in registers; lane 0 holds all 3
// gate pre-acts of element gw -> computes h(gw), release-publishes ONE float.
// Consumers: ONE thread per element per block polls with relaxed (coherent)
// loads, caching already-valid values — minimal poll traffic.
// Verified local optimum: R11 (per-warp full poll), R13 (smem flag chunks),
// R14 (trailing-barrier removal) ALL regressed 2-6x. Do not modify sync.
__global__ void __launch_bounds__(NTHR, 1) chain_k(const float* __restrict__ Wih,
                                                   const float* __restrict__ PE,
                                                   const float* __restrict__ bih,
                                                   const float* __restrict__ bhh,
                                                   float* __restrict__ Hout) {
    __shared__ __align__(16) float sx[HD];
    const int tid = threadIdx.x, lane = tid & 31, wid = tid >> 5;
    const int gw = blockIdx.x * NWARP + wid;   // 0..1023

    // preload 3 weight rows into registers (one-time read)
    float4 wr0[8], wr1[8], wr2[8];
    {
        const float4* w0 = (const float4*)(Wih + (size_t)gw * HD);
        const float4* w1 = (const float4*)(Wih + (size_t)(gw + 2 * HD) * HD);
        const float4* w2 = (const float4*)(Wih + (size_t)(gw + 3 * HD) * HD);
#pragma unroll
        for (int k = 0; k < 8; k++) {
            wr0[k] = w0[lane + 32 * k];
            wr1[k] = w1[lane + 32 * k];
            wr2[k] = w2[lane + 32 * k];
        }
    }
    // biases are t-invariant: hoisted out of the loop entirely
    float bi = 0.0f, bg = 0.0f, bo = 0.0f;
    if (lane == 0) {
        bi = bih[gw] + bhh[gw];
        bg = bih[gw + 2 * HD] + bhh[gw + 2 * HD];
        bo = bih[gw + 3 * HD] + bhh[gw + 3 * HD];
    }

    for (int t = 0; t < SEQ; t++) {
        // pe(t): independent of the poll -> issued first, latency hidden
        float4 pe = __ldg((const float4*)(PE + (size_t)t * HD) + tid);

        float v0 = 0.0f, v1 = 0.0f, v2 = 0.0f, v3 = 0.0f;
        if (t > 0) {
            const float* src = Hout + (size_t)(t - 1) * HD + tid * 4;
            v0 = ld_relaxed(src + 0); v1 = ld_relaxed(src + 1);
            v2 = ld_relaxed(src + 2); v3 = ld_relaxed(src + 3);
            while (v0 == FLAGF || v1 == FLAGF || v2 == FLAGF || v3 == FLAGF) {
                if (v0 == FLAGF) v0 = ld_relaxed(src + 0);
                if (v1 == FLAGF) v1 = ld_relaxed(src + 1);
                if (v2 == FLAGF) v2 = ld_relaxed(src + 2);
                if (v3 == FLAGF) v3 = ld_relaxed(src + 3);
            }
        }
        sx[tid * 4 + 0] = v0 + pe.x; sx[tid * 4 + 1] = v1 + pe.y;
        sx[tid * 4 + 2] = v2 + pe.z; sx[tid * 4 + 3] = v3 + pe.w;
        __syncthreads();

        float r0 = 0.0f, r1 = 0.0f, r2 = 0.0f;
        const float4* p = (const float4*)sx;
#pragma unroll
        for (int k = 0; k < 8; k++) {
            float4 x = p[lane + 32 * k];
            r0 = fmaf(wr0[k].x, x.x, r0); r0 = fmaf(wr0[k].y, x.y, r0);
            r0 = fmaf(wr0[k].z, x.z, r0); r0 = fmaf(wr0[k].w, x.w, r0);
            r1 = fmaf(wr1[k].x, x.x, r1); r1 = fmaf(wr1[k].y, x.y, r1);
            r1 = fmaf(wr1[k].z, x.z, r1); r1 = fmaf(wr1[k].w, x.w, r1);
            r2 = fmaf(wr2[k].x, x.x, r2); r2 = fmaf(wr2[k].y, x.y, r2);
            r2 = fmaf(wr2[k].z, x.z, r2); r2 = fmaf(wr2[k].w, x.w, r2);
        }
#pragma unroll
        for (int o = 16; o; o >>= 1) {
            r0 += __shfl_xor_sync(0xffffffffu, r0, o);
            r1 += __shfl_xor_sync(0xffffffffu, r1, o);
            r2 += __shfl_xor_sync(0xffffffffu, r2, o);
        }
        if (lane == 0) {
            float hv = sigm_fast(r2 + bo) *
                       tanh_fast(sigm_fast(r0 + bi) * tanh_fast(r1 + bg));
            st_release(&Hout[(size_t)t * HD + gw], hv);   // coherent publish
        }
        __syncthreads();    // protect sx before next iteration's overwrite
    }
}

// ---------------- epilogue ----------------
__global__ void __launch_bounds__(NTHR) k_epi(float* __restrict__ out) {
    __shared__ float sred[NWARP];
    const int tid = threadIdx.x;
    const size_t last = (size_t)(SEQ - 1) * HD;
    for (int i = tid; i < HD; i += NTHR) {
        out[i] = 0.0f;                              // pred level 0 == 0
        out[1 * HD + i] = B_P1[last + i];
        out[2 * HD + i] = B_P2[last + i];
        out[3 * HD + i] = B_P3[last + i];
        out[4 * HD + i] = B_ENC0[last + i];         // err level 0 = enc0
        out[5 * HD + i] = B_ENC1[last + i];
        out[6 * HD + i] = B_ENC2[last + i];
        out[7 * HD + i] = B_ENC3[last + i];
    }
    float s = 0.0f;
    for (int t = tid; t < SEQ; t += NTHR)
        s += B_fe[t] + B_fe[SEQ + t] + B_fe[2 * SEQ + t] + B_fe[3 * SEQ + t];
    s = block_reduce(s, sred);
    if (tid == 0) out[8 * HD] = s;
}

// ---------------- launch ----------------
extern "C" void kernel_launch(void* const* d_in, const int* in_sizes, int n_in,
                              void* d_out, int out_size) {
    (void)n_in; (void)out_size;
    const float *obs, *pw1, *pb1, *pw2, *pb2, *ew1, *eb1, *ew2, *eb2;
    const float *qw, *qb, *wih, *bih, *bhh;
    if (in_sizes[0] == SEQ * HD) {
        obs = (const float*)d_in[0];
        pw1 = (const float*)d_in[1];  pb1 = (const float*)d_in[2];
        pw2 = (const float*)d_in[3];  pb2 = (const float*)d_in[4];
        ew1 = (const float*)d_in[5];  eb1 = (const float*)d_in[6];
        ew2 = (const float*)d_in[7];  eb2 = (const float*)d_in[8];
        qw  = (const float*)d_in[9];  qb  = (const float*)d_in[10];
        wih = (const float*)d_in[11];  // whh unused
        bih = (const float*)d_in[13]; bhh = (const float*)d_in[14];
    } else {
        bhh = (const float*)d_in[0];  bih = (const float*)d_in[1];
        eb1 = (const float*)d_in[2];  eb2 = (const float*)d_in[3];
        ew1 = (const float*)d_in[4];  ew2 = (const float*)d_in[5];
        obs = (const float*)d_in[6];
        pb1 = (const float*)d_in[7];  pb2 = (const float*)d_in[8];
        pw1 = (const float*)d_in[9];  pw2 = (const float*)d_in[10];
        qb  = (const float*)d_in[11]; qw  = (const float*)d_in[12];
        wih = (const float*)d_in[14];  // whh unused
    }
    float* out = (float*)d_out;

    float *bG, *bE0, *bE1, *bE2, *bE3, *bP1, *bP2, *bP3, *bH0, *bH1, *bH2, *bPE;
    float *bDOT, *bFE;
    cudaGetSymbolAddress((void**)&bG,  B_G);
    cudaGetSymbolAddress((void**)&bE0, B_ENC0);
    cudaGetSymbolAddress((void**)&bE1, B_ENC1);
    cudaGetSymbolAddress((void**)&bE2, B_ENC2);
    cudaGetSymbolAddress((void**)&bE3, B_ENC3);
    cudaGetSymbolAddress((void**)&bP1, B_P1);
    cudaGetSymbolAddress((void**)&bP2, B_P2);
    cudaGetSymbolAddress((void**)&bP3, B_P3);
    cudaGetSymbolAddress((void**)&bH0, B_H0);
    cudaGetSymbolAddress((void**)&bH1, B_H1);
    cudaGetSymbolAddress((void**)&bH2, B_H2);
    cudaGetSymbolAddress((void**)&bPE, B_PE);
    cudaGetSymbolAddress((void**)&bDOT, B_DOT);
    cudaGetSymbolAddress((void**)&bFE, B_fe);

    float* bH[3]  = {bH0, bH1, bH2};
    float* bEN[4] = {bE0, bE1, bE2, bE3};
    float* bP[4]  = {nullptr, bP1, bP2, bP3};

    const dim3 gg(HD / 64, SEQ / 64);        // (16, 8) = 128 blocks

    // reset h buffers to FLAG + zero fe (must run first every replay)
    flag_fill<<<(SEQ * HD + NTHR - 1) / NTHR, NTHR>>>();

    // ---- level 0 precompute ----
    gemm_k<<<gg, 256>>>(ew1, eb1, obs, nullptr, bG, 1,
                        nullptr, nullptr, nullptr, nullptr, nullptr, nullptr);
    gemm_k<<<gg, 256>>>(ew2, eb2, bG, nullptr, bE0, 0,
                        nullptr, nullptr, nullptr, nullptr, nullptr, nullptr);
    lvl0_aux<<<SEQ, NTHR>>>(obs, qw, qb);
    chain_k<<<NBLK, NTHR>>>(wih, bPE, bih, bhh, bH0);

    // ---- levels 1..3 ----
    for (int l = 1; l < NLVL; l++) {
        const float* pw1l = pw1 + (size_t)l * HD * HD;
        const float* pw2l = pw2 + (size_t)l * HD * HD;
        const float* ew1l = ew1 + (size_t)l * HD * HD;
        const float* ew2l = ew2 + (size_t)l * HD * HD;
        const float* wihl = wih + (size_t)l * 4 * HD * HD;

        gemm_k<<<gg, 256>>>(pw1l, pb1 + l * HD, bH[l - 1], nullptr, bG, 1,
                            nullptr, nullptr, nullptr, nullptr, nullptr, nullptr);
        gemm_k<<<gg, 256>>>(pw2l, pb2 + l * HD, bG, nullptr, bP[l], 0,
                            nullptr, nullptr, nullptr, nullptr, nullptr, nullptr);
        // ew1: A = enc_{l-1} - pred_l (err); fused dot(err, qw_l) -> B_DOT
        gemm_k<<<gg, 256>>>(ew1l, eb1 + l * HD, bEN[l - 1], bP[l], bG, 1,
                            qw + l * HD, bDOT, nullptr, nullptr, nullptr, nullptr);
        // ew2: out = enc_l; fused prec/PE/fe epilogue
        gemm_k<<<gg, 256>>>(ew2l, eb2 + l * HD, bG, nullptr, bEN[l], 0,
                            nullptr, nullptr, bDOT, qb + l, bPE, bFE + l * SEQ);
        if (l < 3) {
            chain_k<<<NBLK, NTHR>>>(wihl, bPE,
                                    bih + (size_t)l * 4 * HD,
                                    bhh + (size_t)l * 4 * HD, bH[l]);
        }
    }
    k_epi<<<1, NTHR>>>(out);
}

// round 17
// speedup vs baseline: 1.0092x; 1.0092x over previous
#include <cuda_runtime.h>
#include <math.h>

#define NLVL 4
#define HD   1024
#define SEQ  512
#define NBLK 128
#define NTHR 256
#define NWARP 8
#define FLAGF 2.0f            // impossible h value: |h| < 1 always

// ---------------- device scratch (static, no allocation) ----------------
__device__ __align__(16) float B_G   [SEQ * HD];      // gelu intermediate buffer
__device__ __align__(16) float B_ENC0[SEQ * HD];
__device__ __align__(16) float B_ENC1[SEQ * HD];
__device__ __align__(16) float B_ENC2[SEQ * HD];
__device__ __align__(16) float B_ENC3[SEQ * HD];
__device__ __align__(16) float B_P1  [SEQ * HD];
__device__ __align__(16) float B_P2  [SEQ * HD];
__device__ __align__(16) float B_P3  [SEQ * HD];
__device__ __align__(16) float B_H0  [SEQ * HD];
__device__ __align__(16) float B_H1  [SEQ * HD];
__device__ __align__(16) float B_H2  [SEQ * HD];
__device__ __align__(16) float B_PE  [SEQ * HD];      // prec * enc (per level, reused)
__device__ float B_DOT[SEQ];                           // err.qw per t (per level, reused)
__device__ float B_fe [4 * SEQ];                       // per-level per-t fe terms

// ---------------- helpers ----------------
__device__ __forceinline__ float gelu_f(float x) {
    return 0.5f * x * (1.0f + erff(x * 0.7071067811865475f));
}
__device__ __forceinline__ float sigm(float x) {
    return 1.0f / (1.0f + __expf(-x));
}
// fast MUFU-based activations (~1e-6 rel err, 3 orders inside budget)
__device__ __forceinline__ float sigm_fast(float x) {
    return __fdividef(1.0f, 1.0f + __expf(-x));
}
__device__ __forceinline__ float tanh_fast(float x) {
    return 1.0f - __fdividef(2.0f, __expf(2.0f * x) + 1.0f);
}

// morally-strong (coherent) GPU-scope ops — per-location coherence is only
// guaranteed for .relaxed/.acquire/.release scoped ops (weak .cg reads stale).
__device__ __forceinline__ float ld_relaxed(const float* p) {
    float v;
    asm volatile("ld.relaxed.gpu.global.f32 %0, [%1];" : "=f"(v) : "l"(p) : "memory");
    return v;
}
__device__ __forceinline__ void st_release(float* p, float v) {
    asm volatile("st.release.gpu.global.f32 [%0], %1;" :: "l"(p), "f"(v) : "memory");
}

// block reduce; result valid in thread 0
__device__ __forceinline__ float block_reduce(float v, float* sred) {
#pragma unroll
    for (int o = 16; o; o >>= 1) v += __shfl_xor_sync(0xffffffffu, v, o);
    int w = threadIdx.x >> 5;
    if ((threadIdx.x & 31) == 0) sred[w] = v;
    __syncthreads();
    if (threadIdx.x < 32) {
        v = (threadIdx.x < NWARP) ? sred[threadIdx.x] : 0.0f;
#pragma unroll
        for (int o = 4; o; o >>= 1) v += __shfl_xor_sync(0xffffffffu, v, o);
    }
    __syncthreads();
    return v;
}

// ---------------- flag prefill + fe zero (runs every replay, first) ------
__global__ void flag_fill() {
    size_t i = (size_t)blockIdx.x * blockDim.x + threadIdx.x;
    if (i < (size_t)SEQ * HD) {
        B_H0[i] = FLAGF; B_H1[i] = FLAGF; B_H2[i] = FLAGF;
    }
    if (i < 3 * SEQ) B_fe[SEQ + i] = 0.0f;   // zero levels 1..3 fe accumulators
}

// ---------------- tiled GEMM: 64 timesteps x 32 rows, double-buffered ----
// (R15-proven config: 256 blocks, 13KB smem)  out[t][r] = act(W[r]·x_t + b[r])
// x_t = inA[t] (- inB[t] if inB).
// Optional fused stages:
//  qwl/dotout   (ew1 mode): x-column-0 blocks also compute dot(x_t, qwl) per t
//                           (x is the err vector) -> dotout[t], no atomics.
//  dotin/qbl/peout/feout (ew2 mode): epilogue computes prec=sigm(dot+qb),
//                           stores PE = out*prec, atomically accumulates
//                           fe[t] += prec * sum(out^2).
__global__ void __launch_bounds__(256) gemm_k(
    const float* __restrict__ W,    const float* __restrict__ bias,
    const float* __restrict__ inA,  const float* __restrict__ inB,
    float* __restrict__ outp, int out_gelu,
    const float* __restrict__ qwl,  float* __restrict__ dotout,
    const float* __restrict__ dotin, const float* __restrict__ qbl,
    float* __restrict__ peout, float* __restrict__ feout) {
    __shared__ __align__(16) float As[2][16][68];   // [buf][k][t]
    __shared__ __align__(16) float Bs[2][16][34];   // [buf][k][r]
    const int tid = threadIdx.x;
    const int bm = blockIdx.y * 64;              // timestep tile
    const int bn = blockIdx.x * 32;              // row tile
    const int tm = (tid >> 4) << 2;              // 4 t per thread
    const int tn = (tid & 15) << 1;              // 2 rows per thread
    const int lrow = tid >> 2, lk = (tid & 3) << 2;

    const float* Arow = inA + (size_t)(bm + lrow) * HD;
    const float* Brow = inB ? (inB + (size_t)(bm + lrow) * HD) : nullptr;
    const float* Wrow = W + (size_t)(bn + (tid >> 2)) * HD;  // valid for tid<128
    const bool dodot = (dotout != nullptr) && (blockIdx.x == 0);
    float dq = 0.0f;

    // prologue: load tile 0 into buffer 0
    {
        float4 a = *(const float4*)(Arow + lk);
        if (Brow) {
            float4 b2 = *(const float4*)(Brow + lk);
            a.x -= b2.x; a.y -= b2.y; a.z -= b2.z; a.w -= b2.w;
        }
        if (dodot) {
            float4 q = *(const float4*)(qwl + lk);
            dq = a.x * q.x + a.y * q.y + a.z * q.z + a.w * q.w;
        }
        As[0][lk + 0][lrow] = a.x; As[0][lk + 1][lrow] = a.y;
        As[0][lk + 2][lrow] = a.z; As[0][lk + 3][lrow] = a.w;
        if (tid < 128) {
            float4 w4 = *(const float4*)(Wrow + lk);
            Bs[0][lk + 0][lrow] = w4.x; Bs[0][lk + 1][lrow] = w4.y;
            Bs[0][lk + 2][lrow] = w4.z; Bs[0][lk + 3][lrow] = w4.w;
        }
    }
    __syncthreads();

    float acc[4][2] = {};
#pragma unroll 2
    for (int i = 0; i < HD / 16; i++) {
        const int buf = i & 1;
        const bool more = (i + 1 < HD / 16);
        // prefetch tile i+1 into registers (overlaps with compute below)
        float4 an = make_float4(0.f, 0.f, 0.f, 0.f);
        float4 wn = make_float4(0.f, 0.f, 0.f, 0.f);
        if (more) {
            const int k0 = (i + 1) * 16;
            an = *(const float4*)(Arow + k0 + lk);
            if (Brow) {
                float4 b2 = *(const float4*)(Brow + k0 + lk);
                an.x -= b2.x; an.y -= b2.y; an.z -= b2.z; an.w -= b2.w;
            }
            if (dodot) {
                float4 q = *(const float4*)(qwl + k0 + lk);
                dq += an.x * q.x + an.y * q.y + an.z * q.z + an.w * q.w;
            }
            if (tid < 128) wn = *(const float4*)(Wrow + k0 + lk);
        }
        // compute on buffer buf
#pragma unroll
        for (int k = 0; k < 16; k++) {
            float4 a4 = *(const float4*)&As[buf][k][tm];
            float2 b2 = *(const float2*)&Bs[buf][k][tn];
            acc[0][0] = fmaf(a4.x, b2.x, acc[0][0]);
            acc[0][1] = fmaf(a4.x, b2.y, acc[0][1]);
            acc[1][0] = fmaf(a4.y, b2.x, acc[1][0]);
            acc[1][1] = fmaf(a4.y, b2.y, acc[1][1]);
            acc[2][0] = fmaf(a4.z, b2.x, acc[2][0]);
            acc[2][1] = fmaf(a4.z, b2.y, acc[2][1]);
            acc[3][0] = fmaf(a4.w, b2.x, acc[3][0]);
            acc[3][1] = fmaf(a4.w, b2.y, acc[3][1]);
        }
        if (more) {
            const int nb = buf ^ 1;
            As[nb][lk + 0][lrow] = an.x; As[nb][lk + 1][lrow] = an.y;
            As[nb][lk + 2][lrow] = an.z; As[nb][lk + 3][lrow] = an.w;
            if (tid < 128) {
                Bs[nb][lk + 0][lrow] = wn.x; Bs[nb][lk + 1][lrow] = wn.y;
                Bs[nb][lk + 2][lrow] = wn.z; Bs[nb][lk + 3][lrow] = wn.w;
            }
            __syncthreads();
        }
    }

    // fused dot reduction (4 threads per t, consecutive lanes)
    if (dodot) {
        dq += __shfl_xor_sync(0xffffffffu, dq, 1);
        dq += __shfl_xor_sync(0xffffffffu, dq, 2);
        if ((tid & 3) == 0) dotout[bm + lrow] = dq;
    }

    const float b0 = bias[bn + tn], b1 = bias[bn + tn + 1];
    const float qb0 = qbl ? __ldg(qbl) : 0.0f;
#pragma unroll
    for (int i = 0; i < 4; i++) {
        float v0 = acc[i][0] + b0;
        float v1 = acc[i][1] + b1;
        if (out_gelu) { v0 = gelu_f(v0); v1 = gelu_f(v1); }
        const int t = bm + tm + i;
        *(float2*)&outp[(size_t)t * HD + bn + tn] = make_float2(v0, v1);
        if (peout) {
            float prec = sigm_fast(__ldg(&dotin[t]) + qb0);
            *(float2*)&peout[(size_t)t * HD + bn + tn] =
                make_float2(v0 * prec, v1 * prec);
            atomicAdd(&feout[t], prec * (v0 * v0 + v1 * v1));
        }
    }
}

// ---------------- level-0 aux: prec0/PE0/fe0 (unchanged, proven) ---------
__global__ void __launch_bounds__(NTHR) lvl0_aux(const float* __restrict__ obs,
                                                 const float* __restrict__ qw,
                                                 const float* __restrict__ qb) {
    __shared__ float sred[NWARP];
    __shared__ float sprec;
    const int t = blockIdx.x, tid = threadIdx.x;
    float d = 0.0f;
    for (int i = tid; i < HD; i += NTHR)
        d = fmaf(obs[(size_t)t * HD + i], qw[i], d);
    d = block_reduce(d, sred);
    if (tid == 0) sprec = sigm(d + qb[0]);
    __syncthreads();
    float prec = sprec, s = 0.0f;
    for (int i = tid; i < HD; i += NTHR) {
        float e = B_ENC0[(size_t)t * HD + i];
        B_PE[(size_t)t * HD + i] = e * prec;
        s = fmaf(e, e, s);
    }
    s = block_reduce(s, sred);
    if (tid == 0) B_fe[t] = s * prec;
}

// ---------------- sequential LSTM chain (round-12 proven; FROZEN) ---------
// gates(t) = wih @ (h(t-1) + pe(t)) + (bih+bhh)  [C-GEMM folded in].
// warp gw owns W rows {gw, gw+2HD, gw+3HD} in registers; lane 0 holds all 3
// gate pre-acts of element gw -> computes h(gw), release-publishes ONE float.
// Consumers: ONE thread per element per block polls with relaxed (coherent)
// loads, caching already-valid values — minimal poll traffic.
// Verified local optimum: R11 (per-warp full poll), R13 (smem flag chunks),
// R14 (trailing-barrier removal) ALL regressed 2-6x. Do not modify sync.
__global__ void __launch_bounds__(NTHR, 1) chain_k(const float* __restrict__ Wih,
                                                   const float* __restrict__ PE,
                                                   const float* __restrict__ bih,
                                                   const float* __restrict__ bhh,
                                                   float* __restrict__ Hout) {
    __shared__ __align__(16) float sx[HD];
    const int tid = threadIdx.x, lane = tid & 31, wid = tid >> 5;
    const int gw = blockIdx.x * NWARP + wid;   // 0..1023

    // preload 3 weight rows into registers (one-time read)
    float4 wr0[8], wr1[8], wr2[8];
    {
        const float4* w0 = (const float4*)(Wih + (size_t)gw * HD);
        const float4* w1 = (const float4*)(Wih + (size_t)(gw + 2 * HD) * HD);
        const float4* w2 = (const float4*)(Wih + (size_t)(gw + 3 * HD) * HD);
#pragma unroll
        for (int k = 0; k < 8; k++) {
            wr0[k] = w0[lane + 32 * k];
            wr1[k] = w1[lane + 32 * k];
            wr2[k] = w2[lane + 32 * k];
        }
    }
    // biases are t-invariant: hoisted out of the loop entirely
    float bi = 0.0f, bg = 0.0f, bo = 0.0f;
    if (lane == 0) {
        bi = bih[gw] + bhh[gw];
        bg = bih[gw + 2 * HD] + bhh[gw + 2 * HD];
        bo = bih[gw + 3 * HD] + bhh[gw + 3 * HD];
    }

    for (int t = 0; t < SEQ; t++) {
        // pe(t): independent of the poll -> issued first, latency hidden
        float4 pe = __ldg((const float4*)(PE + (size_t)t * HD) + tid);

        float v0 = 0.0f, v1 = 0.0f, v2 = 0.0f, v3 = 0.0f;
        if (t > 0) {
            const float* src = Hout + (size_t)(t - 1) * HD + tid * 4;
            v0 = ld_relaxed(src + 0); v1 = ld_relaxed(src + 1);
            v2 = ld_relaxed(src + 2); v3 = ld_relaxed(src + 3);
            while (v0 == FLAGF || v1 == FLAGF || v2 == FLAGF || v3 == FLAGF) {
                if (v0 == FLAGF) v0 = ld_relaxed(src + 0);
                if (v1 == FLAGF) v1 = ld_relaxed(src + 1);
                if (v2 == FLAGF) v2 = ld_relaxed(src + 2);
                if (v3 == FLAGF) v3 = ld_relaxed(src + 3);
            }
        }
        sx[tid * 4 + 0] = v0 + pe.x; sx[tid * 4 + 1] = v1 + pe.y;
        sx[tid * 4 + 2] = v2 + pe.z; sx[tid * 4 + 3] = v3 + pe.w;
        __syncthreads();

        float r0 = 0.0f, r1 = 0.0f, r2 = 0.0f;
        const float4* p = (const float4*)sx;
#pragma unroll
        for (int k = 0; k < 8; k++) {
            float4 x = p[lane + 32 * k];
            r0 = fmaf(wr0[k].x, x.x, r0); r0 = fmaf(wr0[k].y, x.y, r0);
            r0 = fmaf(wr0[k].z, x.z, r0); r0 = fmaf(wr0[k].w, x.w, r0);
            r1 = fmaf(wr1[k].x, x.x, r1); r1 = fmaf(wr1[k].y, x.y, r1);
            r1 = fmaf(wr1[k].z, x.z, r1); r1 = fmaf(wr1[k].w, x.w, r1);
            r2 = fmaf(wr2[k].x, x.x, r2); r2 = fmaf(wr2[k].y, x.y, r2);
            r2 = fmaf(wr2[k].z, x.z, r2); r2 = fmaf(wr2[k].w, x.w, r2);
        }
#pragma unroll
        for (int o = 16; o; o >>= 1) {
            r0 += __shfl_xor_sync(0xffffffffu, r0, o);
            r1 += __shfl_xor_sync(0xffffffffu, r1, o);
            r2 += __shfl_xor_sync(0xffffffffu, r2, o);
        }
        if (lane == 0) {
            float hv = sigm_fast(r2 + bo) *
                       tanh_fast(sigm_fast(r0 + bi) * tanh_fast(r1 + bg));
            st_release(&Hout[(size_t)t * HD + gw], hv);   // coherent publish
        }
        __syncthreads();    // protect sx before next iteration's overwrite
    }
}

// ---------------- epilogue ----------------
__global__ void __launch_bounds__(NTHR) k_epi(float* __restrict__ out) {
    __shared__ float sred[NWARP];
    const int tid = threadIdx.x;
    const size_t last = (size_t)(SEQ - 1) * HD;
    for (int i = tid; i < HD; i += NTHR) {
        out[i] = 0.0f;                              // pred level 0 == 0
        out[1 * HD + i] = B_P1[last + i];
        out[2 * HD + i] = B_P2[last + i];
        out[3 * HD + i] = B_P3[last + i];
        out[4 * HD + i] = B_ENC0[last + i];         // err level 0 = enc0
        out[5 * HD + i] = B_ENC1[last + i];
        out[6 * HD + i] = B_ENC2[last + i];
        out[7 * HD + i] = B_ENC3[last + i];
    }
    float s = 0.0f;
    for (int t = tid; t < SEQ; t += NTHR)
        s += B_fe[t] + B_fe[SEQ + t] + B_fe[2 * SEQ + t] + B_fe[3 * SEQ + t];
    s = block_reduce(s, sred);
    if (tid == 0) out[8 * HD] = s;
}

// ---------------- launch ----------------
extern "C" void kernel_launch(void* const* d_in, const int* in_sizes, int n_in,
                              void* d_out, int out_size) {
    (void)n_in; (void)out_size;
    const float *obs, *pw1, *pb1, *pw2, *pb2, *ew1, *eb1, *ew2, *eb2;
    const float *qw, *qb, *wih, *bih, *bhh;
    if (in_sizes[0] == SEQ * HD) {
        obs = (const float*)d_in[0];
        pw1 = (const float*)d_in[1];  pb1 = (const float*)d_in[2];
        pw2 = (const float*)d_in[3];  pb2 = (const float*)d_in[4];
        ew1 = (const float*)d_in[5];  eb1 = (const float*)d_in[6];
        ew2 = (const float*)d_in[7];  eb2 = (const float*)d_in[8];
        qw  = (const float*)d_in[9];  qb  = (const float*)d_in[10];
        wih = (const float*)d_in[11];  // whh unused
        bih = (const float*)d_in[13]; bhh = (const float*)d_in[14];
    } else {
        bhh = (const float*)d_in[0];  bih = (const float*)d_in[1];
        eb1 = (const float*)d_in[2];  eb2 = (const float*)d_in[3];
        ew1 = (const float*)d_in[4];  ew2 = (const float*)d_in[5];
        obs = (const float*)d_in[6];
        pb1 = (const float*)d_in[7];  pb2 = (const float*)d_in[8];
        pw1 = (const float*)d_in[9];  pw2 = (const float*)d_in[10];
        qb  = (const float*)d_in[11]; qw  = (const float*)d_in[12];
        wih = (const float*)d_in[14];  // whh unused
    }
    float* out = (float*)d_out;

    float *bG, *bE0, *bE1, *bE2, *bE3, *bP1, *bP2, *bP3, *bH0, *bH1, *bH2, *bPE;
    float *bDOT, *bFE;
    cudaGetSymbolAddress((void**)&bG,  B_G);
    cudaGetSymbolAddress((void**)&bE0, B_ENC0);
    cudaGetSymbolAddress((void**)&bE1, B_ENC1);
    cudaGetSymbolAddress((void**)&bE2, B_ENC2);
    cudaGetSymbolAddress((void**)&bE3, B_ENC3);
    cudaGetSymbolAddress((void**)&bP1, B_P1);
    cudaGetSymbolAddress((void**)&bP2, B_P2);
    cudaGetSymbolAddress((void**)&bP3, B_P3);
    cudaGetSymbolAddress((void**)&bH0, B_H0);
    cudaGetSymbolAddress((void**)&bH1, B_H1);
    cudaGetSymbolAddress((void**)&bH2, B_H2);
    cudaGetSymbolAddress((void**)&bPE, B_PE);
    cudaGetSymbolAddress((void**)&bDOT, B_DOT);
    cudaGetSymbolAddress((void**)&bFE, B_fe);

    float* bH[3]  = {bH0, bH1, bH2};
    float* bEN[4] = {bE0, bE1, bE2, bE3};
    float* bP[4]  = {nullptr, bP1, bP2, bP3};

    const dim3 gg(HD / 32, SEQ / 64);        // (32, 8) = 256 blocks (R15-proven)

    // reset h buffers to FLAG + zero fe (must run first every replay)
    flag_fill<<<(SEQ * HD + NTHR - 1) / NTHR, NTHR>>>();

    // ---- level 0 precompute ----
    gemm_k<<<gg, 256>>>(ew1, eb1, obs, nullptr, bG, 1,
                        nullptr, nullptr, nullptr, nullptr, nullptr, nullptr);
    gemm_k<<<gg, 256>>>(ew2, eb2, bG, nullptr, bE0, 0,
                        nullptr, nullptr, nullptr, nullptr, nullptr, nullptr);
    lvl0_aux<<<SEQ, NTHR>>>(obs, qw, qb);
    chain_k<<<NBLK, NTHR>>>(wih, bPE, bih, bhh, bH0);

    // ---- levels 1..3 ----
    for (int l = 1; l < NLVL; l++) {
        const float* pw1l = pw1 + (size_t)l * HD * HD;
        const float* pw2l = pw2 + (size_t)l * HD * HD;
        const float* ew1l = ew1 + (size_t)l * HD * HD;
        const float* ew2l = ew2 + (size_t)l * HD * HD;
        const float* wihl = wih + (size_t)l * 4 * HD * HD;

        gemm_k<<<gg, 256>>>(pw1l, pb1 + l * HD, bH[l - 1], nullptr, bG, 1,
                            nullptr, nullptr, nullptr, nullptr, nullptr, nullptr);
        gemm_k<<<gg, 256>>>(pw2l, pb2 + l * HD, bG, nullptr, bP[l], 0,
                            nullptr, nullptr, nullptr, nullptr, nullptr, nullptr);
        // ew1: A = enc_{l-1} - pred_l (err); fused dot(err, qw_l) -> B_DOT
        gemm_k<<<gg, 256>>>(ew1l, eb1 + l * HD, bEN[l - 1], bP[l], bG, 1,
                            qw + l * HD, bDOT, nullptr, nullptr, nullptr, nullptr);
        // ew2: out = enc_l; fused prec/PE/fe epilogue
        gemm_k<<<gg, 256>>>(ew2l, eb2 + l * HD, bG, nullptr, bEN[l], 0,
                            nullptr, nullptr, bDOT, qb + l, bPE, bFE + l * SEQ);
        if (l < 3) {
            chain_k<<<NBLK, NTHR>>>(wihl, bPE,
                                    bih + (size_t)l * 4 * HD,
                                    bhh + (size_t)l * 4 * HD, bH[l]);
        }
    }
    k_epi<<<1, NTHR>>>(out);
}